// round 1
// baseline (speedup 1.0000x reference)
#include <cuda_runtime.h>
#include <cuda_bf16.h>
#include <cstdint>

// Problem constants (B=4, T=4096, C=1024, H=16, D=64, BLOCK=128)
#define B_   4
#define T_   4096
#define C_   1024
#define H_   16
#define Dh_  64
#define BS_  128
#define M_TOK (B_ * T_)        // 16384
#define N_QKV (3 * C_)         // 3072

// Scratch (allocation-free rule: __device__ globals)
__device__ float g_qkv[(size_t)M_TOK * N_QKV];   // 192 MiB
__device__ float g_attn[(size_t)M_TOK * C_];     // 64 MiB

// ---------------------------------------------------------------------------
// SGEMM: C = A[M,K] @ B[K,N] (+bias).  BM=BN=128, BK=8, 256 threads, 8x8/thread
// M,N multiples of 128; K multiple of 8.
// ---------------------------------------------------------------------------
template <bool BIAS>
__global__ __launch_bounds__(256, 2)
void sgemm128(const float* __restrict__ A, const float* __restrict__ Bm,
              const float* __restrict__ bias, float* __restrict__ C,
              int M, int N, int K)
{
    __shared__ float As[8][128];   // As[k][m] (transposed for coalesced compute)
    __shared__ float Bs[8][128];   // Bs[k][n]

    const int bm = blockIdx.y * 128;
    const int bn = blockIdx.x * 128;
    const int tid = threadIdx.x;

    const int tm = (tid >> 4) << 3;   // 0..120
    const int tn = (tid & 15) << 3;   // 0..120

    // load mappings
    const int arow = tid >> 1;            // 0..127
    const int acol = (tid & 1) << 2;      // 0 or 4
    const int brow = tid >> 5;            // 0..7
    const int bcol = (tid & 31) << 2;     // 0..124

    const float* Aptr = A + (size_t)(bm + arow) * K + acol;
    const float* Bptr = Bm + (size_t)brow * N + bn + bcol;

    float acc[8][8] = {};

    for (int k0 = 0; k0 < K; k0 += 8) {
        float4 a4 = *(const float4*)(Aptr + k0);
        As[acol + 0][arow] = a4.x;
        As[acol + 1][arow] = a4.y;
        As[acol + 2][arow] = a4.z;
        As[acol + 3][arow] = a4.w;
        float4 b4 = *(const float4*)(Bptr + (size_t)k0 * N);
        *(float4*)&Bs[brow][bcol] = b4;
        __syncthreads();

#pragma unroll
        for (int kk = 0; kk < 8; kk++) {
            float4 a0 = *(const float4*)&As[kk][tm];
            float4 a1 = *(const float4*)&As[kk][tm + 4];
            float4 b0 = *(const float4*)&Bs[kk][tn];
            float4 b1 = *(const float4*)&Bs[kk][tn + 4];
            float ar[8] = {a0.x, a0.y, a0.z, a0.w, a1.x, a1.y, a1.z, a1.w};
            float br[8] = {b0.x, b0.y, b0.z, b0.w, b1.x, b1.y, b1.z, b1.w};
#pragma unroll
            for (int i = 0; i < 8; i++)
#pragma unroll
                for (int j = 0; j < 8; j++)
                    acc[i][j] = fmaf(ar[i], br[j], acc[i][j]);
        }
        __syncthreads();
    }

#pragma unroll
    for (int i = 0; i < 8; i++) {
#pragma unroll
        for (int j = 0; j < 8; j += 4) {
            float4 v;
            v.x = acc[i][j + 0];
            v.y = acc[i][j + 1];
            v.z = acc[i][j + 2];
            v.w = acc[i][j + 3];
            if (BIAS) {
                v.x += bias[bn + tn + j + 0];
                v.y += bias[bn + tn + j + 1];
                v.z += bias[bn + tn + j + 2];
                v.w += bias[bn + tn + j + 3];
            }
            *(float4*)(C + (size_t)(bm + tm + i) * N + bn + tn + j) = v;
        }
    }
}

// ---------------------------------------------------------------------------
// Block-local causal attention. grid = (H, T/BS, B), 256 threads.
// qkv layout: [token][3C] with q at col h*64, k at C + h*64, v at 2C + h*64.
// Dyn smem: S[128][132] | Qt[64][132], Kt[64][132] (Vs[128][68] reuses Qt/Kt).
// ---------------------------------------------------------------------------
#define S_PITCH 132
#define V_PITCH 68
#define ATTN_SMEM_FLOATS (128 * S_PITCH + 2 * 64 * S_PITCH)

__global__ __launch_bounds__(256)
void attn_kernel(const float* __restrict__ qkv, float* __restrict__ out)
{
    const int h   = blockIdx.x;
    const int blk = blockIdx.y;
    const int b   = blockIdx.z;
    const int token0 = b * T_ + blk * BS_;

    const float* qp = qkv + (size_t)token0 * N_QKV + h * Dh_;
    const float* kp = qp + C_;
    const float* vp = qp + 2 * C_;

    extern __shared__ float sm[];
    float* S  = sm;                       // [128][132]
    float* Qt = sm + 128 * S_PITCH;       // [64][132] (k-major: Qt[k][r])
    float* Kt = Qt + 64 * S_PITCH;
    float* Vs = Qt;                       // [128][68] reuse after S is built

    const int tid = threadIdx.x;

    // Load Q,K transposed into smem
    for (int i = tid; i < BS_ * Dh_; i += 256) {
        int r = i >> 6, c = i & 63;
        float qv = qp[(size_t)r * N_QKV + c];
        float kv = kp[(size_t)r * N_QKV + c];
        Qt[c * S_PITCH + r] = qv;
        Kt[c * S_PITCH + r] = kv;
    }
    __syncthreads();

    // S = (Q K^T) * 1/8, 8x8 per thread
    const int tm = (tid >> 4) << 3;
    const int tn = (tid & 15) << 3;
    float acc[8][8] = {};
#pragma unroll 4
    for (int k = 0; k < Dh_; k++) {
        float4 a0 = *(const float4*)&Qt[k * S_PITCH + tm];
        float4 a1 = *(const float4*)&Qt[k * S_PITCH + tm + 4];
        float4 b0 = *(const float4*)&Kt[k * S_PITCH + tn];
        float4 b1 = *(const float4*)&Kt[k * S_PITCH + tn + 4];
        float ar[8] = {a0.x, a0.y, a0.z, a0.w, a1.x, a1.y, a1.z, a1.w};
        float br[8] = {b0.x, b0.y, b0.z, b0.w, b1.x, b1.y, b1.z, b1.w};
#pragma unroll
        for (int i = 0; i < 8; i++)
#pragma unroll
            for (int j = 0; j < 8; j++)
                acc[i][j] = fmaf(ar[i], br[j], acc[i][j]);
    }

    // Row-wise masked softmax. Row (tm+i) is shared by the 16 lanes with the
    // same tid>>4 (lanes tn=0..15, aligned 16-lane groups within a warp).
    const float scale = 0.125f;  // 1/sqrt(64)
#pragma unroll
    for (int i = 0; i < 8; i++) {
        const int row = tm + i;
        float rmax = -1e30f;
#pragma unroll
        for (int j = 0; j < 8; j++) {
            float s = acc[i][j] * scale;
            bool valid = (tn + j) <= row;
            acc[i][j] = valid ? s : -1e30f;
            rmax = fmaxf(rmax, acc[i][j]);
        }
#pragma unroll
        for (int o = 8; o > 0; o >>= 1)
            rmax = fmaxf(rmax, __shfl_xor_sync(0xffffffffu, rmax, o));
        float rsum = 0.f;
#pragma unroll
        for (int j = 0; j < 8; j++) {
            float e = ((tn + j) <= row) ? __expf(acc[i][j] - rmax) : 0.f;
            acc[i][j] = e;
            rsum += e;
        }
#pragma unroll
        for (int o = 8; o > 0; o >>= 1)
            rsum += __shfl_xor_sync(0xffffffffu, rsum, o);
        float inv = __fdividef(1.f, rsum + 1e-6f);
#pragma unroll
        for (int j = 0; j < 8; j++)
            S[row * S_PITCH + tn + j] = acc[i][j] * inv;
    }
    __syncthreads();   // S complete; Qt/Kt now dead

    // Load V (natural layout [k][d])
    for (int i = tid; i < BS_ * Dh_; i += 256) {
        int r = i >> 6, c = i & 63;
        Vs[r * V_PITCH + c] = vp[(size_t)r * N_QKV + c];
    }
    __syncthreads();

    // O = P @ V : per thread 8 rows x 4 cols
    const int vn = (tid & 15) << 2;   // 0..60
    float oacc[8][4] = {};
#pragma unroll 4
    for (int k = 0; k < BS_; k++) {
        float4 v4 = *(const float4*)&Vs[k * V_PITCH + vn];
#pragma unroll
        for (int i = 0; i < 8; i++) {
            float p = S[(tm + i) * S_PITCH + k];
            oacc[i][0] = fmaf(p, v4.x, oacc[i][0]);
            oacc[i][1] = fmaf(p, v4.y, oacc[i][1]);
            oacc[i][2] = fmaf(p, v4.z, oacc[i][2]);
            oacc[i][3] = fmaf(p, v4.w, oacc[i][3]);
        }
    }

    float* op = out + (size_t)token0 * C_ + h * Dh_;
#pragma unroll
    for (int i = 0; i < 8; i++) {
        float4 v;
        v.x = oacc[i][0]; v.y = oacc[i][1]; v.z = oacc[i][2]; v.w = oacc[i][3];
        *(float4*)(op + (size_t)(tm + i) * C_ + vn) = v;
    }
}

// ---------------------------------------------------------------------------
extern "C" void kernel_launch(void* const* d_in, const int* in_sizes, int n_in,
                              void* d_out, int out_size)
{
    const float* x      = (const float*)d_in[0];   // [4,4096,1024]
    const float* W_qkv  = (const float*)d_in[1];   // [1024,3072]
    const float* W_proj = (const float*)d_in[2];   // [1024,1024]
    const float* b_proj = (const float*)d_in[3];   // [1024]
    float* out = (float*)d_out;                    // [4,4096,1024]

    float* qkv;  cudaGetSymbolAddress((void**)&qkv,  g_qkv);
    float* attn; cudaGetSymbolAddress((void**)&attn, g_attn);

    static bool smem_set = false;
    if (!smem_set) {
        cudaFuncSetAttribute(attn_kernel,
                             cudaFuncAttributeMaxDynamicSharedMemorySize,
                             ATTN_SMEM_FLOATS * sizeof(float));
        smem_set = true;
    }

    // 1) qkv = x @ W_qkv
    {
        dim3 grid(N_QKV / 128, M_TOK / 128);
        sgemm128<false><<<grid, 256>>>(x, W_qkv, nullptr, qkv, M_TOK, N_QKV, C_);
    }
    // 2) block-local causal attention
    {
        dim3 grid(H_, T_ / BS_, B_);
        attn_kernel<<<grid, 256, ATTN_SMEM_FLOATS * sizeof(float)>>>(qkv, attn);
    }
    // 3) out = attn @ W_proj + b_proj
    {
        dim3 grid(C_ / 128, M_TOK / 128);
        sgemm128<true><<<grid, 256>>>(attn, W_proj, b_proj, out, M_TOK, C_, C_);
    }
}

// round 3
// speedup vs baseline: 3.4938x; 3.4938x over previous
#include <cuda_runtime.h>
#include <cstdint>

// Problem constants (B=4, T=4096, C=1024, H=16, D=64, BLOCK=128)
#define B_    4
#define T_    4096
#define C_    1024
#define H_    16
#define Dh_   64
#define BS_   128
#define M_TOK 16384
#define N_QKV 3072
#define KDIM  1024

// Scratch (allocation-free rule: __device__ globals)
__device__ float g_qkv   [(size_t)M_TOK * N_QKV];   // 192 MiB
__device__ float g_attn  [(size_t)M_TOK * C_];      // 64 MiB (tf32-rounded)
__device__ float g_xc    [(size_t)M_TOK * C_];      // 64 MiB (tf32-rounded x)
__device__ float g_Wqkvc [(size_t)C_ * N_QKV];      // 12 MiB (tf32-rounded)
__device__ float g_Wprojc[(size_t)C_ * C_];         // 4 MiB  (tf32-rounded)

// ---------------------------------------------------------------------------
// helpers
// ---------------------------------------------------------------------------
__device__ __forceinline__ uint32_t smem_u32(const void* p) {
    uint32_t a;
    asm("{ .reg .u64 t; cvta.to.shared.u64 t, %1; cvt.u32.u64 %0, t; }" : "=r"(a) : "l"(p));
    return a;
}
__device__ __forceinline__ float tf32r(float x) {
    uint32_t r;
    asm("cvt.rna.tf32.f32 %0, %1;" : "=r"(r) : "f"(x));
    return __uint_as_float(r);
}
// D += A*B, m16n8k8 tf32
__device__ __forceinline__ void mma_tf32(float* d, const uint32_t* a, const uint32_t* b) {
    asm volatile(
        "mma.sync.aligned.m16n8k8.row.col.f32.tf32.tf32.f32 "
        "{%0,%1,%2,%3}, {%4,%5,%6,%7}, {%8,%9}, {%0,%1,%2,%3};"
        : "+f"(d[0]), "+f"(d[1]), "+f"(d[2]), "+f"(d[3])
        : "r"(a[0]), "r"(a[1]), "r"(a[2]), "r"(a[3]), "r"(b[0]), "r"(b[1]));
}
#define CP16(dst, src) \
    asm volatile("cp.async.cg.shared.global [%0], [%1], 16;" :: "r"(dst), "l"(src))
#define CP_COMMIT() asm volatile("cp.async.commit_group;")
#define CP_WAIT1()  asm volatile("cp.async.wait_group 1;")

// ---------------------------------------------------------------------------
// elementwise tf32 rounding pass
// ---------------------------------------------------------------------------
__global__ void cvt_tf32_k(const float4* __restrict__ in, float4* __restrict__ out, int n4) {
    int i = blockIdx.x * blockDim.x + threadIdx.x;
    if (i < n4) {
        float4 v = in[i];
        v.x = tf32r(v.x); v.y = tf32r(v.y); v.z = tf32r(v.z); v.w = tf32r(v.w);
        out[i] = v;
    }
}

// ---------------------------------------------------------------------------
// tf32 mma.sync GEMM: C[M,N] = A[M,1024] @ B[1024,N] (+bias)
// 128x128x32 tiles, 3-stage cp.async pipeline, 8 warps (2x4), 64x32 warp tile.
// Inputs A, B must already be tf32-rounded.
// ---------------------------------------------------------------------------
#define GSTG    3
#define APITCH  36     // [m][k] pad: bank = (4m + k) % 32 -> conflict-free frags
#define BPITCH  136    // [k][n] pad: bank = (8k + n) % 32 -> conflict-free frags
#define ASTG_F  (128 * APITCH)            // 4608 floats
#define BSTG_F  (32 * BPITCH)             // 4352 floats
#define STG_F   (ASTG_F + BSTG_F)         // 8960 floats
#define GSMEM_B (GSTG * STG_F * 4)        // 107520 bytes

template <bool BIAS>
__global__ __launch_bounds__(256, 2)
void gemm_mma(const float* __restrict__ A, const float* __restrict__ Bw,
              const float* __restrict__ bias, float* __restrict__ C, int N)
{
    extern __shared__ float sm[];
    const uint32_t sb = smem_u32(sm);
    const int tid = threadIdx.x, lane = tid & 31, wid = tid >> 5;
    const int wm = wid >> 2, wn = wid & 3, gr = lane >> 2, ctg = lane & 3;
    const int bm = blockIdx.y * 128, bn = blockIdx.x * 128;

    auto load_tile = [&](int s, int k0) {
        uint32_t sA = sb + (uint32_t)(s * STG_F * 4);
        uint32_t sB = sA + ASTG_F * 4;
#pragma unroll
        for (int i = 0; i < 4; i++) {                  // A tile: 128 x 32
            int ch = tid + i * 256;
            int r = ch >> 3, kc = (ch & 7) << 2;
            CP16(sA + (uint32_t)(r * APITCH + kc) * 4,
                 A + (size_t)(bm + r) * KDIM + k0 + kc);
        }
#pragma unroll
        for (int i = 0; i < 4; i++) {                  // B tile: 32 x 128
            int ch = tid + i * 256;
            int kr = ch >> 5, nc = (ch & 31) << 2;
            CP16(sB + (uint32_t)(kr * BPITCH + nc) * 4,
                 Bw + (size_t)(k0 + kr) * N + bn + nc);
        }
    };

    load_tile(0, 0);  CP_COMMIT();
    load_tile(1, 32); CP_COMMIT();

    float acc[4][4][4] = {};

    for (int it = 0; it < 32; ++it) {
        const int s = it % 3;
        CP_WAIT1();
        __syncthreads();
        if (it + 2 < 32) load_tile((it + 2) % 3, (it + 2) * 32);
        CP_COMMIT();

        const float* As = sm + s * STG_F;
        const float* Bs = As + ASTG_F;
#pragma unroll
        for (int kk = 0; kk < 4; ++kk) {
            const int kb = kk * 8;
            uint32_t a[4][4], bfr[4][2];
#pragma unroll
            for (int mi = 0; mi < 4; ++mi) {
                int r = wm * 64 + mi * 16 + gr;
                a[mi][0] = __float_as_uint(As[(r    ) * APITCH + kb + ctg]);
                a[mi][1] = __float_as_uint(As[(r + 8) * APITCH + kb + ctg]);
                a[mi][2] = __float_as_uint(As[(r    ) * APITCH + kb + ctg + 4]);
                a[mi][3] = __float_as_uint(As[(r + 8) * APITCH + kb + ctg + 4]);
            }
#pragma unroll
            for (int ni = 0; ni < 4; ++ni) {
                int c = wn * 32 + ni * 8 + gr;
                bfr[ni][0] = __float_as_uint(Bs[(kb + ctg    ) * BPITCH + c]);
                bfr[ni][1] = __float_as_uint(Bs[(kb + ctg + 4) * BPITCH + c]);
            }
#pragma unroll
            for (int mi = 0; mi < 4; ++mi)
#pragma unroll
                for (int ni = 0; ni < 4; ++ni)
                    mma_tf32(acc[mi][ni], a[mi], bfr[ni]);
        }
    }

    // epilogue (c-frag: rows gr, gr+8; cols 2*ctg, 2*ctg+1)
#pragma unroll
    for (int mi = 0; mi < 4; mi++) {
        int r0 = bm + wm * 64 + mi * 16 + gr;
#pragma unroll
        for (int ni = 0; ni < 4; ni++) {
            int c0 = bn + wn * 32 + ni * 8 + 2 * ctg;
            float bx = 0.f, by = 0.f;
            if (BIAS) { bx = bias[c0]; by = bias[c0 + 1]; }
            float2 v0 = make_float2(acc[mi][ni][0] + bx, acc[mi][ni][1] + by);
            float2 v1 = make_float2(acc[mi][ni][2] + bx, acc[mi][ni][3] + by);
            *(float2*)&C[(size_t)r0 * N + c0]       = v0;
            *(float2*)&C[(size_t)(r0 + 8) * N + c0] = v1;
        }
    }
}

// ---------------------------------------------------------------------------
// Block-local causal attention with tf32 mma.sync.
// grid = (H, T/128, B), 256 threads (8 warps, 2x4).
// Writes tf32-rounded output (consumed by GEMM2 as a tf32 operand).
// ---------------------------------------------------------------------------
#define QP 68     // Q/K/V pitch: bank = (4r + c) % 32 -> conflict-free
#define PP 132    // P pitch
#define OFF_Q 0
#define OFF_K (128 * QP)                  // 8704
#define OFF_V 0                            // V reuses Q region after S is done
#define OFF_P (2 * 128 * QP)               // 17408
#define OFF_R (OFF_P + 128 * PP)           // 34304 (red[128][4])
#define ATT_F (OFF_R + 512)                // 34816 floats
#define ATT_B (ATT_F * 4)                  // 139264 bytes

__global__ __launch_bounds__(256, 1)
void attn_mma(const float* __restrict__ qkv, float* __restrict__ outp)
{
    extern __shared__ float sm[];
    const int h = blockIdx.x, blk = blockIdx.y, b = blockIdx.z;
    const int token0 = b * T_ + blk * BS_;
    const float* qp = qkv + (size_t)token0 * N_QKV + h * Dh_;
    const float* kp = qp + C_;
    const float* vp = qp + 2 * C_;

    const int tid = threadIdx.x, lane = tid & 31, wid = tid >> 5;
    const int wm = wid >> 2, wn = wid & 3, gr = lane >> 2, ctg = lane & 3;

    float* Qs  = sm + OFF_Q;
    float* Ks  = sm + OFF_K;
    float* Vs  = sm + OFF_V;
    float* Ps  = sm + OFF_P;
    float* red = sm + OFF_R;

    // load Q, K (tf32-rounded)
    for (int i = tid; i < 2048; i += 256) {
        int r = i >> 4, c4 = (i & 15) << 2;
        float4 q = *(const float4*)(qp + (size_t)r * N_QKV + c4);
        float4 k = *(const float4*)(kp + (size_t)r * N_QKV + c4);
        q.x = tf32r(q.x); q.y = tf32r(q.y); q.z = tf32r(q.z); q.w = tf32r(q.w);
        k.x = tf32r(k.x); k.y = tf32r(k.y); k.z = tf32r(k.z); k.w = tf32r(k.w);
        *(float4*)&Qs[r * QP + c4] = q;
        *(float4*)&Ks[r * QP + c4] = k;
    }
    __syncthreads();

    // S = Q @ K^T (warp tile 64x32, k = 64)
    float acc[4][4][4] = {};
#pragma unroll
    for (int kk = 0; kk < 8; ++kk) {
        const int kb = kk * 8;
        uint32_t a[4][4], bfr[4][2];
#pragma unroll
        for (int mi = 0; mi < 4; ++mi) {
            int r = wm * 64 + mi * 16 + gr;
            a[mi][0] = __float_as_uint(Qs[(r    ) * QP + kb + ctg]);
            a[mi][1] = __float_as_uint(Qs[(r + 8) * QP + kb + ctg]);
            a[mi][2] = __float_as_uint(Qs[(r    ) * QP + kb + ctg + 4]);
            a[mi][3] = __float_as_uint(Qs[(r + 8) * QP + kb + ctg + 4]);
        }
#pragma unroll
        for (int ni = 0; ni < 4; ++ni) {
            int c = wn * 32 + ni * 8 + gr;
            bfr[ni][0] = __float_as_uint(Ks[c * QP + kb + ctg]);
            bfr[ni][1] = __float_as_uint(Ks[c * QP + kb + ctg + 4]);
        }
#pragma unroll
        for (int mi = 0; mi < 4; ++mi)
#pragma unroll
            for (int ni = 0; ni < 4; ++ni)
                mma_tf32(acc[mi][ni], a[mi], bfr[ni]);
    }

    // masked exp (no max-subtraction: |scores| ~ O(1)); warp-partial row sums
    float rsum[4][2] = {};
#pragma unroll
    for (int mi = 0; mi < 4; ++mi) {
#pragma unroll
        for (int ni = 0; ni < 4; ++ni) {
#pragma unroll
            for (int e = 0; e < 4; ++e) {
                int row = wm * 64 + mi * 16 + gr + ((e >= 2) ? 8 : 0);
                int col = wn * 32 + ni * 8 + 2 * ctg + (e & 1);
                float v = (col <= row) ? __expf(acc[mi][ni][e] * 0.125f) : 0.f;
                acc[mi][ni][e] = v;
                rsum[mi][e >> 1 & 1] += (e >= 2) ? 0.f : v;   // placeholder, fixed below
            }
        }
    }
    // recompute partial sums cleanly (rows: half 0 -> gr, half 1 -> gr+8)
#pragma unroll
    for (int mi = 0; mi < 4; ++mi) { rsum[mi][0] = 0.f; rsum[mi][1] = 0.f; }
#pragma unroll
    for (int mi = 0; mi < 4; ++mi)
#pragma unroll
        for (int ni = 0; ni < 4; ++ni) {
            rsum[mi][0] += acc[mi][ni][0] + acc[mi][ni][1];
            rsum[mi][1] += acc[mi][ni][2] + acc[mi][ni][3];
        }
#pragma unroll
    for (int mi = 0; mi < 4; ++mi)
#pragma unroll
        for (int hl = 0; hl < 2; ++hl) {
            float s = rsum[mi][hl];
            s += __shfl_xor_sync(0xffffffffu, s, 1);
            s += __shfl_xor_sync(0xffffffffu, s, 2);
            rsum[mi][hl] = s;
        }
    if (ctg == 0) {
#pragma unroll
        for (int mi = 0; mi < 4; ++mi)
#pragma unroll
            for (int hl = 0; hl < 2; ++hl)
                red[(wm * 64 + mi * 16 + gr + hl * 8) * 4 + wn] = rsum[mi][hl];
    }
    __syncthreads();   // everyone done with Qs/Ks reads + red writes

    // fill V (overwrites Q region), tf32-rounded
    for (int i = tid; i < 2048; i += 256) {
        int r = i >> 4, c4 = (i & 15) << 2;
        float4 v = *(const float4*)(vp + (size_t)r * N_QKV + c4);
        v.x = tf32r(v.x); v.y = tf32r(v.y); v.z = tf32r(v.z); v.w = tf32r(v.w);
        *(float4*)&Vs[r * QP + c4] = v;
    }

    // P = e / (rowsum + 1e-6), tf32-rounded into Ps
#pragma unroll
    for (int mi = 0; mi < 4; ++mi)
#pragma unroll
        for (int hl = 0; hl < 2; ++hl) {
            int row = wm * 64 + mi * 16 + gr + hl * 8;
            float ssum = red[row * 4 + 0] + red[row * 4 + 1]
                       + red[row * 4 + 2] + red[row * 4 + 3];
            float inv = __fdividef(1.f, ssum + 1e-6f);
#pragma unroll
            for (int ni = 0; ni < 4; ++ni) {
                float2 pv;
                pv.x = tf32r(acc[mi][ni][hl * 2 + 0] * inv);
                pv.y = tf32r(acc[mi][ni][hl * 2 + 1] * inv);
                *(float2*)&Ps[row * PP + wn * 32 + ni * 8 + 2 * ctg] = pv;
            }
        }
    __syncthreads();

    // O = P @ V (warp tile 64x16, k = 128)
    float oa[4][2][4] = {};
#pragma unroll
    for (int kk = 0; kk < 16; ++kk) {
        const int kb = kk * 8;
        uint32_t a[4][4], bfr[2][2];
#pragma unroll
        for (int mi = 0; mi < 4; ++mi) {
            int r = wm * 64 + mi * 16 + gr;
            a[mi][0] = __float_as_uint(Ps[(r    ) * PP + kb + ctg]);
            a[mi][1] = __float_as_uint(Ps[(r + 8) * PP + kb + ctg]);
            a[mi][2] = __float_as_uint(Ps[(r    ) * PP + kb + ctg + 4]);
            a[mi][3] = __float_as_uint(Ps[(r + 8) * PP + kb + ctg + 4]);
        }
#pragma unroll
        for (int ni = 0; ni < 2; ++ni) {
            int c = wn * 16 + ni * 8 + gr;
            bfr[ni][0] = __float_as_uint(Vs[(kb + ctg    ) * QP + c]);
            bfr[ni][1] = __float_as_uint(Vs[(kb + ctg + 4) * QP + c]);
        }
#pragma unroll
        for (int mi = 0; mi < 4; ++mi)
#pragma unroll
            for (int ni = 0; ni < 2; ++ni)
                mma_tf32(oa[mi][ni], a[mi], bfr[ni]);
    }

    // store (tf32-rounded: feeds GEMM2 as tf32 operand)
    float* op = outp + (size_t)token0 * C_ + h * Dh_;
#pragma unroll
    for (int mi = 0; mi < 4; ++mi) {
        int r0 = wm * 64 + mi * 16 + gr;
#pragma unroll
        for (int ni = 0; ni < 2; ++ni) {
            int c0 = wn * 16 + ni * 8 + 2 * ctg;
            float2 v0 = make_float2(tf32r(oa[mi][ni][0]), tf32r(oa[mi][ni][1]));
            float2 v1 = make_float2(tf32r(oa[mi][ni][2]), tf32r(oa[mi][ni][3]));
            *(float2*)&op[(size_t)r0 * C_ + c0]       = v0;
            *(float2*)&op[(size_t)(r0 + 8) * C_ + c0] = v1;
        }
    }
}

// ---------------------------------------------------------------------------
extern "C" void kernel_launch(void* const* d_in, const int* in_sizes, int n_in,
                              void* d_out, int out_size)
{
    const float* x      = (const float*)d_in[0];
    const float* W_qkv  = (const float*)d_in[1];
    const float* W_proj = (const float*)d_in[2];
    const float* b_proj = (const float*)d_in[3];
    float* out = (float*)d_out;

    float *qkv, *attn, *xc, *Wqkvc, *Wprojc;
    cudaGetSymbolAddress((void**)&qkv,    g_qkv);
    cudaGetSymbolAddress((void**)&attn,   g_attn);
    cudaGetSymbolAddress((void**)&xc,     g_xc);
    cudaGetSymbolAddress((void**)&Wqkvc,  g_Wqkvc);
    cudaGetSymbolAddress((void**)&Wprojc, g_Wprojc);

    static bool attr_set = false;
    if (!attr_set) {
        cudaFuncSetAttribute(gemm_mma<false>,
                             cudaFuncAttributeMaxDynamicSharedMemorySize, GSMEM_B);
        cudaFuncSetAttribute(gemm_mma<true>,
                             cudaFuncAttributeMaxDynamicSharedMemorySize, GSMEM_B);
        cudaFuncSetAttribute(attn_mma,
                             cudaFuncAttributeMaxDynamicSharedMemorySize, ATT_B);
        attr_set = true;
    }

    // 0) tf32-round inputs (rna)
    cvt_tf32_k<<<(M_TOK * C_ / 4 + 255) / 256, 256>>>((const float4*)x, (float4*)xc, M_TOK * C_ / 4);
    cvt_tf32_k<<<(C_ * N_QKV / 4 + 255) / 256, 256>>>((const float4*)W_qkv, (float4*)Wqkvc, C_ * N_QKV / 4);
    cvt_tf32_k<<<(C_ * C_ / 4 + 255) / 256, 256>>>((const float4*)W_proj, (float4*)Wprojc, C_ * C_ / 4);

    // 1) qkv = x @ W_qkv (tf32 mma.sync)
    gemm_mma<false><<<dim3(N_QKV / 128, M_TOK / 128), 256, GSMEM_B>>>(
        xc, Wqkvc, nullptr, qkv, N_QKV);

    // 2) block-local causal attention (tf32 mma.sync)
    attn_mma<<<dim3(H_, T_ / BS_, B_), 256, ATT_B>>>(qkv, attn);

    // 3) out = attn @ W_proj + b_proj (tf32 mma.sync)
    gemm_mma<true><<<dim3(C_ / 128, M_TOK / 128), 256, GSMEM_B>>>(
        attn, Wprojc, b_proj, out, C_);
}

// round 4
// speedup vs baseline: 5.5561x; 1.5903x over previous
#include <cuda_runtime.h>
#include <cuda_fp16.h>
#include <cstdint>

// Problem constants (B=4, T=4096, C=1024, H=16, D=64, BLOCK=128)
#define B_    4
#define T_    4096
#define C_    1024
#define H_    16
#define Dh_   64
#define BS_   128
#define M_TOK 16384
#define N_QKV 3072
#define KDIM  1024

// Scratch (allocation-free rule: __device__ globals)
__device__ __half g_qkvh  [(size_t)M_TOK * N_QKV];  // 96 MiB
__device__ __half g_attnh [(size_t)M_TOK * C_];     // 32 MiB
__device__ __half g_xh    [(size_t)M_TOK * C_];     // 32 MiB
__device__ __half g_WqkvT [(size_t)N_QKV * KDIM];   // 6 MiB  [N][K]
__device__ __half g_WprojT[(size_t)C_ * KDIM];      // 2 MiB  [N][K]

// ---------------------------------------------------------------------------
// helpers
// ---------------------------------------------------------------------------
__device__ __forceinline__ uint32_t smem_u32(const void* p) {
    uint32_t a;
    asm("{ .reg .u64 t; cvta.to.shared.u64 t, %1; cvt.u32.u64 %0, t; }" : "=r"(a) : "l"(p));
    return a;
}
// D += A*B, m16n8k16 f16 inputs, f32 accum
__device__ __forceinline__ void mma_f16(float* d, const uint32_t* a, const uint32_t* b) {
    asm volatile(
        "mma.sync.aligned.m16n8k16.row.col.f32.f16.f16.f32 "
        "{%0,%1,%2,%3}, {%4,%5,%6,%7}, {%8,%9}, {%0,%1,%2,%3};"
        : "+f"(d[0]), "+f"(d[1]), "+f"(d[2]), "+f"(d[3])
        : "r"(a[0]), "r"(a[1]), "r"(a[2]), "r"(a[3]), "r"(b[0]), "r"(b[1]));
}
#define CP16(dst, src) \
    asm volatile("cp.async.cg.shared.global [%0], [%1], 16;" :: "r"(dst), "l"(src))
#define CP_COMMIT() asm volatile("cp.async.commit_group;")
#define CP_WAIT1()  asm volatile("cp.async.wait_group 1;")

// ---------------------------------------------------------------------------
// conversion kernels
// ---------------------------------------------------------------------------
__global__ void cvt_f2h(const float4* __restrict__ in, uint2* __restrict__ out, int n4) {
    int i = blockIdx.x * blockDim.x + threadIdx.x;
    if (i < n4) {
        float4 v = in[i];
        __half2 h0 = __floats2half2_rn(v.x, v.y);
        __half2 h1 = __floats2half2_rn(v.z, v.w);
        out[i] = make_uint2(*(uint32_t*)&h0, *(uint32_t*)&h1);
    }
}
// in fp32 [R][Cc] -> out half [Cc][R]
__global__ void transpose_cvt(const float* __restrict__ in, __half* __restrict__ out,
                              int R, int Cc)
{
    __shared__ float t[32][33];
    int x = blockIdx.x * 32 + threadIdx.x;
    int y = blockIdx.y * 32 + threadIdx.y;
#pragma unroll
    for (int j = 0; j < 32; j += 8)
        t[threadIdx.y + j][threadIdx.x] = in[(size_t)(y + j) * Cc + x];
    __syncthreads();
    int x2 = blockIdx.y * 32 + threadIdx.x;
    int y2 = blockIdx.x * 32 + threadIdx.y;
#pragma unroll
    for (int j = 0; j < 32; j += 8)
        out[(size_t)(y2 + j) * R + x2] = __float2half(t[threadIdx.x][threadIdx.y + j]);
}

// ---------------------------------------------------------------------------
// fp16 mma GEMM: C[M,N] = A[M,1024] @ Bt[N,1024]^T (+bias).
// A half [M][K] row-major, Bt half [N][K] row-major (K-major).
// 128x128 tiles, BK=32 halves, 3-stage cp.async, 8 warps (2x4), 64x32 warp tile.
// ---------------------------------------------------------------------------
#define GP      40                         // smem pitch (halves); 20r+ctg mod 32 distinct
#define ASTG_H  (128 * GP)                 // 5120 halves
#define STG_H   (2 * ASTG_H)               // 10240 halves (A + B)
#define GSMEM_B (3 * STG_H * 2)            // 61440 bytes

template <bool BIAS, bool HALF_OUT>
__global__ __launch_bounds__(256, 2)
void gemm_h(const __half* __restrict__ A, const __half* __restrict__ Bt,
            const float* __restrict__ bias, void* __restrict__ Cout, int N)
{
    extern __shared__ __half smh[];
    const uint32_t sb = smem_u32(smh);
    const int tid = threadIdx.x, lane = tid & 31, wid = tid >> 5;
    const int wm = wid >> 2, wn = wid & 3, gr = lane >> 2, ctg = lane & 3;
    const int bm = blockIdx.y * 128, bn = blockIdx.x * 128;

    auto load_tile = [&](int s, int k0) {
        uint32_t sA = sb + (uint32_t)(s * STG_H * 2);
        uint32_t sB = sA + ASTG_H * 2;
#pragma unroll
        for (int i = 0; i < 2; i++) {              // A: 128 x 32 halves
            int ch = tid + i * 256;
            int r = ch >> 2, kc = (ch & 3) << 3;
            CP16(sA + (uint32_t)(r * GP + kc) * 2,
                 A + (size_t)(bm + r) * KDIM + k0 + kc);
        }
#pragma unroll
        for (int i = 0; i < 2; i++) {              // B: 128 x 32 halves
            int ch = tid + i * 256;
            int r = ch >> 2, kc = (ch & 3) << 3;
            CP16(sB + (uint32_t)(r * GP + kc) * 2,
                 Bt + (size_t)(bn + r) * KDIM + k0 + kc);
        }
    };

    load_tile(0, 0);  CP_COMMIT();
    load_tile(1, 32); CP_COMMIT();

    float acc[4][4][4] = {};

    for (int it = 0; it < 32; ++it) {
        const int s = it % 3;
        CP_WAIT1();
        __syncthreads();
        if (it + 2 < 32) load_tile((it + 2) % 3, (it + 2) * 32);
        CP_COMMIT();

        const __half* As = smh + s * STG_H;
        const __half* Bs = As + ASTG_H;
#pragma unroll
        for (int kk = 0; kk < 2; ++kk) {
            const int kb = kk * 16;
            uint32_t a[4][4], bfr[4][2];
#pragma unroll
            for (int mi = 0; mi < 4; ++mi) {
                int r = wm * 64 + mi * 16 + gr;
                a[mi][0] = *(const uint32_t*)&As[(r    ) * GP + kb + 2 * ctg];
                a[mi][1] = *(const uint32_t*)&As[(r + 8) * GP + kb + 2 * ctg];
                a[mi][2] = *(const uint32_t*)&As[(r    ) * GP + kb + 8 + 2 * ctg];
                a[mi][3] = *(const uint32_t*)&As[(r + 8) * GP + kb + 8 + 2 * ctg];
            }
#pragma unroll
            for (int ni = 0; ni < 4; ++ni) {
                int c = wn * 32 + ni * 8 + gr;
                bfr[ni][0] = *(const uint32_t*)&Bs[c * GP + kb + 2 * ctg];
                bfr[ni][1] = *(const uint32_t*)&Bs[c * GP + kb + 8 + 2 * ctg];
            }
#pragma unroll
            for (int mi = 0; mi < 4; ++mi)
#pragma unroll
                for (int ni = 0; ni < 4; ++ni)
                    mma_f16(acc[mi][ni], a[mi], bfr[ni]);
        }
    }

    // epilogue: c-frag rows gr, gr+8; cols 2ctg, 2ctg+1
#pragma unroll
    for (int mi = 0; mi < 4; mi++) {
        int r0 = bm + wm * 64 + mi * 16 + gr;
#pragma unroll
        for (int ni = 0; ni < 4; ni++) {
            int c0 = bn + wn * 32 + ni * 8 + 2 * ctg;
            if (HALF_OUT) {
                __half* C = (__half*)Cout;
                __half2 v0 = __floats2half2_rn(acc[mi][ni][0], acc[mi][ni][1]);
                __half2 v1 = __floats2half2_rn(acc[mi][ni][2], acc[mi][ni][3]);
                *(__half2*)&C[(size_t)r0 * N + c0]       = v0;
                *(__half2*)&C[(size_t)(r0 + 8) * N + c0] = v1;
            } else {
                float* C = (float*)Cout;
                float bx = 0.f, by = 0.f;
                if (BIAS) { bx = bias[c0]; by = bias[c0 + 1]; }
                float2 v0 = make_float2(acc[mi][ni][0] + bx, acc[mi][ni][1] + by);
                float2 v1 = make_float2(acc[mi][ni][2] + bx, acc[mi][ni][3] + by);
                *(float2*)&C[(size_t)r0 * N + c0]       = v0;
                *(float2*)&C[(size_t)(r0 + 8) * N + c0] = v1;
            }
        }
    }
}

// ---------------------------------------------------------------------------
// Block-local causal attention, fp16 mma. grid = (H, T/128, B), 256 threads.
// Reads fp16 qkv, writes fp16 attn output.
// ---------------------------------------------------------------------------
#define QPH 72          // Q/K/V pitch (halves): 36r+ctg mod 32 -> 4r+ctg distinct
#define PPH 136         // P pitch (halves)
#define OFF_Q 0
#define OFF_K (128 * QPH)                    // 9216
#define OFF_P (2 * 128 * QPH)                // 18432
#define OFF_RED_B ((OFF_P + 128 * PPH) * 2)  // bytes: after Ps
#define ATT_B (OFF_RED_B + 128 * 4 * 4)      // + red[128][4] floats

__global__ __launch_bounds__(256, 1)
void attn_h(const __half* __restrict__ qkv, __half* __restrict__ outp)
{
    extern __shared__ __half smh[];
    const int h = blockIdx.x, blk = blockIdx.y, b = blockIdx.z;
    const int token0 = b * T_ + blk * BS_;
    const __half* qp = qkv + (size_t)token0 * N_QKV + h * Dh_;
    const __half* kp = qp + C_;
    const __half* vp = qp + 2 * C_;

    const int tid = threadIdx.x, lane = tid & 31, wid = tid >> 5;
    const int wm = wid >> 2, wn = wid & 3, gr = lane >> 2, ctg = lane & 3;

    __half* Qs = smh + OFF_Q;
    __half* Ks = smh + OFF_K;
    __half* Vs = smh + OFF_Q;                 // reuse Q region after S
    __half* Ps = smh + OFF_P;
    float*  red = (float*)((char*)smh + OFF_RED_B);

    // load Q, K (8 halves per chunk)
    for (int i = tid; i < 1024; i += 256) {
        int r = i >> 3, c8 = (i & 7) << 3;
        *(uint4*)&Qs[r * QPH + c8] = *(const uint4*)(qp + (size_t)r * N_QKV + c8);
        *(uint4*)&Ks[r * QPH + c8] = *(const uint4*)(kp + (size_t)r * N_QKV + c8);
    }
    __syncthreads();

    // S = Q @ K^T (warp tile 64x32, k=64 -> 4 ksteps)
    float acc[4][4][4] = {};
#pragma unroll
    for (int kk = 0; kk < 4; ++kk) {
        const int kb = kk * 16;
        uint32_t a[4][4], bfr[4][2];
#pragma unroll
        for (int mi = 0; mi < 4; ++mi) {
            int r = wm * 64 + mi * 16 + gr;
            a[mi][0] = *(const uint32_t*)&Qs[(r    ) * QPH + kb + 2 * ctg];
            a[mi][1] = *(const uint32_t*)&Qs[(r + 8) * QPH + kb + 2 * ctg];
            a[mi][2] = *(const uint32_t*)&Qs[(r    ) * QPH + kb + 8 + 2 * ctg];
            a[mi][3] = *(const uint32_t*)&Qs[(r + 8) * QPH + kb + 8 + 2 * ctg];
        }
#pragma unroll
        for (int ni = 0; ni < 4; ++ni) {
            int c = wn * 32 + ni * 8 + gr;
            bfr[ni][0] = *(const uint32_t*)&Ks[c * QPH + kb + 2 * ctg];
            bfr[ni][1] = *(const uint32_t*)&Ks[c * QPH + kb + 8 + 2 * ctg];
        }
#pragma unroll
        for (int mi = 0; mi < 4; ++mi)
#pragma unroll
            for (int ni = 0; ni < 4; ++ni)
                mma_f16(acc[mi][ni], a[mi], bfr[ni]);
    }

    // masked exp (scores O(1): no max subtraction needed) + row sums
    float rsum[4][2];
#pragma unroll
    for (int mi = 0; mi < 4; ++mi) { rsum[mi][0] = 0.f; rsum[mi][1] = 0.f; }
#pragma unroll
    for (int mi = 0; mi < 4; ++mi)
#pragma unroll
        for (int ni = 0; ni < 4; ++ni)
#pragma unroll
            for (int e = 0; e < 4; ++e) {
                int row = wm * 64 + mi * 16 + gr + ((e >= 2) ? 8 : 0);
                int col = wn * 32 + ni * 8 + 2 * ctg + (e & 1);
                float v = (col <= row) ? __expf(acc[mi][ni][e] * 0.125f) : 0.f;
                acc[mi][ni][e] = v;
                rsum[mi][e >> 1] += v;
            }
#pragma unroll
    for (int mi = 0; mi < 4; ++mi)
#pragma unroll
        for (int hl = 0; hl < 2; ++hl) {
            float s = rsum[mi][hl];
            s += __shfl_xor_sync(0xffffffffu, s, 1);
            s += __shfl_xor_sync(0xffffffffu, s, 2);
            rsum[mi][hl] = s;
        }
    if (ctg == 0)
#pragma unroll
        for (int mi = 0; mi < 4; ++mi)
#pragma unroll
            for (int hl = 0; hl < 2; ++hl)
                red[(wm * 64 + mi * 16 + gr + hl * 8) * 4 + wn] = rsum[mi][hl];
    __syncthreads();   // Qs/Ks reads done; red complete

    // load V into Q region ([key][d], natural layout)
    for (int i = tid; i < 1024; i += 256) {
        int r = i >> 3, c8 = (i & 7) << 3;
        *(uint4*)&Vs[r * QPH + c8] = *(const uint4*)(vp + (size_t)r * N_QKV + c8);
    }

    // P = e / (rowsum + 1e-6), fp16 into Ps
#pragma unroll
    for (int mi = 0; mi < 4; ++mi)
#pragma unroll
        for (int hl = 0; hl < 2; ++hl) {
            int row = wm * 64 + mi * 16 + gr + hl * 8;
            float ssum = red[row * 4 + 0] + red[row * 4 + 1]
                       + red[row * 4 + 2] + red[row * 4 + 3];
            float inv = __fdividef(1.f, ssum + 1e-6f);
#pragma unroll
            for (int ni = 0; ni < 4; ++ni) {
                __half2 pv = __floats2half2_rn(acc[mi][ni][hl * 2 + 0] * inv,
                                               acc[mi][ni][hl * 2 + 1] * inv);
                *(__half2*)&Ps[row * PPH + wn * 32 + ni * 8 + 2 * ctg] = pv;
            }
        }
    __syncthreads();

    // O = P @ V (warp tile 64x16, k=128 -> 8 ksteps)
    float oa[4][2][4] = {};
#pragma unroll
    for (int kk = 0; kk < 8; ++kk) {
        const int kb = kk * 16;
        uint32_t a[4][4], bfr[2][2];
#pragma unroll
        for (int mi = 0; mi < 4; ++mi) {
            int r = wm * 64 + mi * 16 + gr;
            a[mi][0] = *(const uint32_t*)&Ps[(r    ) * PPH + kb + 2 * ctg];
            a[mi][1] = *(const uint32_t*)&Ps[(r + 8) * PPH + kb + 2 * ctg];
            a[mi][2] = *(const uint32_t*)&Ps[(r    ) * PPH + kb + 8 + 2 * ctg];
            a[mi][3] = *(const uint32_t*)&Ps[(r + 8) * PPH + kb + 8 + 2 * ctg];
        }
#pragma unroll
        for (int ni = 0; ni < 2; ++ni) {
            int n = wn * 16 + ni * 8 + gr;
            {
                __half2 h2 = __halves2half2(Vs[(kb + 2 * ctg    ) * QPH + n],
                                            Vs[(kb + 2 * ctg + 1) * QPH + n]);
                bfr[ni][0] = *(uint32_t*)&h2;
            }
            {
                __half2 h2 = __halves2half2(Vs[(kb + 8 + 2 * ctg    ) * QPH + n],
                                            Vs[(kb + 9 + 2 * ctg    ) * QPH + n]);
                bfr[ni][1] = *(uint32_t*)&h2;
            }
        }
#pragma unroll
        for (int mi = 0; mi < 4; ++mi)
#pragma unroll
            for (int ni = 0; ni < 2; ++ni)
                mma_f16(oa[mi][ni], a[mi], bfr[ni]);
    }

    // store fp16 (feeds GEMM2)
    __half* op = outp + (size_t)token0 * C_ + h * Dh_;
#pragma unroll
    for (int mi = 0; mi < 4; ++mi) {
        int r0 = wm * 64 + mi * 16 + gr;
#pragma unroll
        for (int ni = 0; ni < 2; ++ni) {
            int c0 = wn * 16 + ni * 8 + 2 * ctg;
            __half2 v0 = __floats2half2_rn(oa[mi][ni][0], oa[mi][ni][1]);
            __half2 v1 = __floats2half2_rn(oa[mi][ni][2], oa[mi][ni][3]);
            *(__half2*)&op[(size_t)r0 * C_ + c0]       = v0;
            *(__half2*)&op[(size_t)(r0 + 8) * C_ + c0] = v1;
        }
    }
}

// ---------------------------------------------------------------------------
extern "C" void kernel_launch(void* const* d_in, const int* in_sizes, int n_in,
                              void* d_out, int out_size)
{
    const float* x      = (const float*)d_in[0];
    const float* W_qkv  = (const float*)d_in[1];
    const float* W_proj = (const float*)d_in[2];
    const float* b_proj = (const float*)d_in[3];
    float* out = (float*)d_out;

    __half *qkvh, *attnh, *xh, *WqkvT, *WprojT;
    cudaGetSymbolAddress((void**)&qkvh,   g_qkvh);
    cudaGetSymbolAddress((void**)&attnh,  g_attnh);
    cudaGetSymbolAddress((void**)&xh,     g_xh);
    cudaGetSymbolAddress((void**)&WqkvT,  g_WqkvT);
    cudaGetSymbolAddress((void**)&WprojT, g_WprojT);

    static bool attr_set = false;
    if (!attr_set) {
        cudaFuncSetAttribute((const void*)gemm_h<false, true>,
                             cudaFuncAttributeMaxDynamicSharedMemorySize, GSMEM_B);
        cudaFuncSetAttribute((const void*)gemm_h<true, false>,
                             cudaFuncAttributeMaxDynamicSharedMemorySize, GSMEM_B);
        cudaFuncSetAttribute((const void*)attn_h,
                             cudaFuncAttributeMaxDynamicSharedMemorySize, ATT_B);
        attr_set = true;
    }

    // 0) fp16 conversions
    cvt_f2h<<<(M_TOK * C_ / 4 + 255) / 256, 256>>>((const float4*)x, (uint2*)xh,
                                                   M_TOK * C_ / 4);
    transpose_cvt<<<dim3(N_QKV / 32, KDIM / 32), dim3(32, 8)>>>(W_qkv, WqkvT, KDIM, N_QKV);
    transpose_cvt<<<dim3(C_ / 32, KDIM / 32), dim3(32, 8)>>>(W_proj, WprojT, KDIM, C_);

    // 1) qkv = x @ W_qkv  (fp16 mma, fp16 out)
    gemm_h<false, true><<<dim3(N_QKV / 128, M_TOK / 128), 256, GSMEM_B>>>(
        xh, WqkvT, nullptr, qkvh, N_QKV);

    // 2) block-local causal attention (fp16 mma)
    attn_h<<<dim3(H_, T_ / BS_, B_), 256, ATT_B>>>(qkvh, attnh);

    // 3) out = attn @ W_proj + b_proj (fp16 mma, fp32 out)
    gemm_h<true, false><<<dim3(C_ / 128, M_TOK / 128), 256, GSMEM_B>>>(
        attnh, WprojT, b_proj, out, C_);
}

// round 5
// speedup vs baseline: 6.3799x; 1.1483x over previous
#include <cuda_runtime.h>
#include <cuda_fp16.h>
#include <cstdint>

// Problem constants (B=4, T=4096, C=1024, H=16, D=64, BLOCK=128)
#define B_    4
#define T_    4096
#define C_    1024
#define H_    16
#define Dh_   64
#define BS_   128
#define M_TOK 16384
#define N_QKV 3072
#define KDIM  1024

// Scratch (allocation-free rule: __device__ globals)
__device__ __half g_qkvh  [(size_t)M_TOK * N_QKV];  // 96 MiB
__device__ __half g_attnh [(size_t)M_TOK * C_];     // 32 MiB
__device__ __half g_xh    [(size_t)M_TOK * C_];     // 32 MiB
__device__ __half g_WqkvT [(size_t)N_QKV * KDIM];   // 6 MiB  [N][K]
__device__ __half g_WprojT[(size_t)C_ * KDIM];      // 2 MiB  [N][K]

// ---------------------------------------------------------------------------
// helpers
// ---------------------------------------------------------------------------
__device__ __forceinline__ uint32_t smem_u32(const void* p) {
    uint32_t a;
    asm("{ .reg .u64 t; cvta.to.shared.u64 t, %1; cvt.u32.u64 %0, t; }" : "=r"(a) : "l"(p));
    return a;
}
// D += A*B, m16n8k16 f16 inputs, f32 accum
__device__ __forceinline__ void mma_f16(float* d, const uint32_t* a, const uint32_t* b) {
    asm volatile(
        "mma.sync.aligned.m16n8k16.row.col.f32.f16.f16.f32 "
        "{%0,%1,%2,%3}, {%4,%5,%6,%7}, {%8,%9}, {%0,%1,%2,%3};"
        : "+f"(d[0]), "+f"(d[1]), "+f"(d[2]), "+f"(d[3])
        : "r"(a[0]), "r"(a[1]), "r"(a[2]), "r"(a[3]), "r"(b[0]), "r"(b[1]));
}
#define LDSM4(r0, r1, r2, r3, addr) \
    asm volatile("ldmatrix.sync.aligned.m8n8.x4.shared.b16 {%0,%1,%2,%3}, [%4];" \
                 : "=r"(r0), "=r"(r1), "=r"(r2), "=r"(r3) : "r"(addr))
#define LDSM4T(r0, r1, r2, r3, addr) \
    asm volatile("ldmatrix.sync.aligned.m8n8.x4.trans.shared.b16 {%0,%1,%2,%3}, [%4];" \
                 : "=r"(r0), "=r"(r1), "=r"(r2), "=r"(r3) : "r"(addr))
#define CP16(dst, src) \
    asm volatile("cp.async.cg.shared.global [%0], [%1], 16;" :: "r"(dst), "l"(src))
#define CP_COMMIT() asm volatile("cp.async.commit_group;")
#define CP_WAIT1()  asm volatile("cp.async.wait_group 1;")

// ---------------------------------------------------------------------------
// conversion kernels
// ---------------------------------------------------------------------------
__global__ void cvt_f2h(const float4* __restrict__ in, uint2* __restrict__ out, int n4) {
    int i = blockIdx.x * blockDim.x + threadIdx.x;
    if (i < n4) {
        float4 v = in[i];
        __half2 h0 = __floats2half2_rn(v.x, v.y);
        __half2 h1 = __floats2half2_rn(v.z, v.w);
        out[i] = make_uint2(*(uint32_t*)&h0, *(uint32_t*)&h1);
    }
}
// in fp32 [R][Cc] -> out half [Cc][R]
__global__ void transpose_cvt(const float* __restrict__ in, __half* __restrict__ out,
                              int R, int Cc)
{
    __shared__ float t[32][33];
    int x = blockIdx.x * 32 + threadIdx.x;
    int y = blockIdx.y * 32 + threadIdx.y;
#pragma unroll
    for (int j = 0; j < 32; j += 8)
        t[threadIdx.y + j][threadIdx.x] = in[(size_t)(y + j) * Cc + x];
    __syncthreads();
    int x2 = blockIdx.y * 32 + threadIdx.x;
    int y2 = blockIdx.x * 32 + threadIdx.y;
#pragma unroll
    for (int j = 0; j < 32; j += 8)
        out[(size_t)(y2 + j) * R + x2] = __float2half(t[threadIdx.x][threadIdx.y + j]);
}

// ---------------------------------------------------------------------------
// fp16 mma GEMM: C[M,N] = A[M,1024] @ Bt[N,1024]^T (+bias).
// A half [M][K], Bt half [N][K]. 128x128 tiles, BK=64 halves, 3-stage
// cp.async pipeline, 8 warps (2x4), 64x32 warp tile, ldmatrix fragment loads.
// ---------------------------------------------------------------------------
#define GP2      72                         // smem pitch (halves), 144B rows
#define ASTG2_H  (128 * GP2)                // 9216 halves per operand tile
#define STG2_H   (2 * ASTG2_H)              // A + B
#define STG2_B   (STG2_H * 2)               // 36864 bytes per stage
#define GSMEM_B  (3 * STG2_B)               // 110592 bytes

template <bool BIAS, bool HALF_OUT>
__global__ __launch_bounds__(256, 2)
void gemm_h(const __half* __restrict__ A, const __half* __restrict__ Bt,
            const float* __restrict__ bias, void* __restrict__ Cout, int N)
{
    extern __shared__ __half smh[];
    const uint32_t sb = smem_u32(smh);
    const int tid = threadIdx.x, lane = tid & 31, wid = tid >> 5;
    const int wm = wid >> 2, wn = wid & 3, gr = lane >> 2, ctg = lane & 3;
    const int bm = blockIdx.y * 128, bn = blockIdx.x * 128;

    auto load_tile = [&](int s, int k0) {
        uint32_t sA = sb + (uint32_t)(s * STG2_B);
        uint32_t sB = sA + ASTG2_H * 2;
#pragma unroll
        for (int i = 0; i < 4; i++) {              // A: 128 rows x 64 halves
            int ch = tid + i * 256;
            int r = ch >> 3, kc = (ch & 7) << 3;
            CP16(sA + (uint32_t)(r * GP2 + kc) * 2,
                 A + (size_t)(bm + r) * KDIM + k0 + kc);
        }
#pragma unroll
        for (int i = 0; i < 4; i++) {              // B: 128 rows x 64 halves
            int ch = tid + i * 256;
            int r = ch >> 3, kc = (ch & 7) << 3;
            CP16(sB + (uint32_t)(r * GP2 + kc) * 2,
                 Bt + (size_t)(bn + r) * KDIM + k0 + kc);
        }
    };

    // ldmatrix per-lane base offsets (halves -> bytes at use)
    const uint32_t aOff = (uint32_t)((wm * 64 + (lane & 15)) * GP2 + ((lane >> 4) << 3)) * 2;
    const uint32_t bOff = (uint32_t)((wn * 32 + ((lane & 16) >> 1) + (lane & 7)) * GP2
                                     + ((lane & 8) ? 8 : 0)) * 2;

    load_tile(0, 0);  CP_COMMIT();
    load_tile(1, 64); CP_COMMIT();

    float acc[4][4][4] = {};

    for (int it = 0; it < 16; ++it) {
        const int s = it % 3;
        CP_WAIT1();
        __syncthreads();
        if (it + 2 < 16) load_tile((it + 2) % 3, (it + 2) * 64);
        CP_COMMIT();

        const uint32_t sA = sb + (uint32_t)(s * STG2_B);
        const uint32_t sB = sA + ASTG2_H * 2;
#pragma unroll
        for (int kk = 0; kk < 4; ++kk) {
            const uint32_t kbB = (uint32_t)(kk * 16) * 2;
            uint32_t a[4][4], bfr[4][2];
#pragma unroll
            for (int mi = 0; mi < 4; ++mi)
                LDSM4(a[mi][0], a[mi][1], a[mi][2], a[mi][3],
                      sA + aOff + (uint32_t)(mi * 16 * GP2) * 2 + kbB);
#pragma unroll
            for (int pn = 0; pn < 2; ++pn)
                LDSM4(bfr[2 * pn][0], bfr[2 * pn][1], bfr[2 * pn + 1][0], bfr[2 * pn + 1][1],
                      sB + bOff + (uint32_t)(pn * 16 * GP2) * 2 + kbB);
#pragma unroll
            for (int mi = 0; mi < 4; ++mi)
#pragma unroll
                for (int ni = 0; ni < 4; ++ni)
                    mma_f16(acc[mi][ni], a[mi], bfr[ni]);
        }
    }

    // epilogue: c-frag rows gr, gr+8; cols 2ctg, 2ctg+1
#pragma unroll
    for (int mi = 0; mi < 4; mi++) {
        int r0 = bm + wm * 64 + mi * 16 + gr;
#pragma unroll
        for (int ni = 0; ni < 4; ni++) {
            int c0 = bn + wn * 32 + ni * 8 + 2 * ctg;
            if (HALF_OUT) {
                __half* C = (__half*)Cout;
                __half2 v0 = __floats2half2_rn(acc[mi][ni][0], acc[mi][ni][1]);
                __half2 v1 = __floats2half2_rn(acc[mi][ni][2], acc[mi][ni][3]);
                *(__half2*)&C[(size_t)r0 * N + c0]       = v0;
                *(__half2*)&C[(size_t)(r0 + 8) * N + c0] = v1;
            } else {
                float* C = (float*)Cout;
                float bx = 0.f, by = 0.f;
                if (BIAS) { bx = bias[c0]; by = bias[c0 + 1]; }
                float2 v0 = make_float2(acc[mi][ni][0] + bx, acc[mi][ni][1] + by);
                float2 v1 = make_float2(acc[mi][ni][2] + bx, acc[mi][ni][3] + by);
                *(float2*)&C[(size_t)r0 * N + c0]       = v0;
                *(float2*)&C[(size_t)(r0 + 8) * N + c0] = v1;
            }
        }
    }
}

// ---------------------------------------------------------------------------
// Block-local causal attention, fp16 mma + ldmatrix. grid = (H, T/128, B),
// 256 threads. Reads fp16 qkv, writes fp16 attn output.
// ---------------------------------------------------------------------------
#define QPH 72          // Q/K/V pitch (halves), 144B rows
#define PPH 136         // P pitch (halves), 272B rows
#define OFF_Q 0
#define OFF_K (128 * QPH)                    // 9216
#define OFF_P (2 * 128 * QPH)                // 18432
#define OFF_RED_B ((OFF_P + 128 * PPH) * 2)  // bytes
#define ATT_B (OFF_RED_B + 128 * 4 * 4)

__global__ __launch_bounds__(256, 1)
void attn_h(const __half* __restrict__ qkv, __half* __restrict__ outp)
{
    extern __shared__ __half smh[];
    const uint32_t sbA = smem_u32(smh);
    const int h = blockIdx.x, blk = blockIdx.y, b = blockIdx.z;
    const int token0 = b * T_ + blk * BS_;
    const __half* qp = qkv + (size_t)token0 * N_QKV + h * Dh_;
    const __half* kp = qp + C_;
    const __half* vp = qp + 2 * C_;

    const int tid = threadIdx.x, lane = tid & 31, wid = tid >> 5;
    const int wm = wid >> 2, wn = wid & 3, gr = lane >> 2, ctg = lane & 3;

    __half* Qs = smh + OFF_Q;
    __half* Ks = smh + OFF_K;
    __half* Vs = smh + OFF_Q;                 // reuse Q region after S
    __half* Ps = smh + OFF_P;
    float*  red = (float*)((char*)smh + OFF_RED_B);

    const uint32_t uQ = sbA + OFF_Q * 2;
    const uint32_t uK = sbA + OFF_K * 2;
    const uint32_t uV = uQ;
    const uint32_t uP = sbA + OFF_P * 2;

    // load Q, K (8 halves per chunk)
    for (int i = tid; i < 1024; i += 256) {
        int r = i >> 3, c8 = (i & 7) << 3;
        *(uint4*)&Qs[r * QPH + c8] = *(const uint4*)(qp + (size_t)r * N_QKV + c8);
        *(uint4*)&Ks[r * QPH + c8] = *(const uint4*)(kp + (size_t)r * N_QKV + c8);
    }
    __syncthreads();

    // ldmatrix lane bases
    const uint32_t aOffQ = (uint32_t)((wm * 64 + (lane & 15)) * QPH + ((lane >> 4) << 3)) * 2;
    const uint32_t bOffK = (uint32_t)((wn * 32 + ((lane & 16) >> 1) + (lane & 7)) * QPH
                                      + ((lane & 8) ? 8 : 0)) * 2;
    const uint32_t aOffP = (uint32_t)((wm * 64 + (lane & 15)) * PPH + ((lane >> 4) << 3)) * 2;
    const uint32_t bOffV = (uint32_t)(((lane & 7) + ((lane & 8) ? 8 : 0)) * QPH
                                      + wn * 16 + ((lane & 16) ? 8 : 0)) * 2;

    // S = Q @ K^T (warp tile 64x32, k=64 -> 4 ksteps); skip fully-masked tiles
    float acc[4][4][4] = {};
    const bool liveQK = (wn * 32 <= wm * 64 + 63);
    if (liveQK) {
#pragma unroll
        for (int kk = 0; kk < 4; ++kk) {
            const uint32_t kbB = (uint32_t)(kk * 16) * 2;
            uint32_t a[4][4], bfr[4][2];
#pragma unroll
            for (int mi = 0; mi < 4; ++mi)
                LDSM4(a[mi][0], a[mi][1], a[mi][2], a[mi][3],
                      uQ + aOffQ + (uint32_t)(mi * 16 * QPH) * 2 + kbB);
#pragma unroll
            for (int pn = 0; pn < 2; ++pn)
                LDSM4(bfr[2 * pn][0], bfr[2 * pn][1], bfr[2 * pn + 1][0], bfr[2 * pn + 1][1],
                      uK + bOffK + (uint32_t)(pn * 16 * QPH) * 2 + kbB);
#pragma unroll
            for (int mi = 0; mi < 4; ++mi)
#pragma unroll
                for (int ni = 0; ni < 4; ++ni)
                    mma_f16(acc[mi][ni], a[mi], bfr[ni]);
        }
    }

    // masked exp (scores O(1): no max subtraction needed) + row sums
    float rsum[4][2];
#pragma unroll
    for (int mi = 0; mi < 4; ++mi) { rsum[mi][0] = 0.f; rsum[mi][1] = 0.f; }
#pragma unroll
    for (int mi = 0; mi < 4; ++mi)
#pragma unroll
        for (int ni = 0; ni < 4; ++ni)
#pragma unroll
            for (int e = 0; e < 4; ++e) {
                int row = wm * 64 + mi * 16 + gr + ((e >= 2) ? 8 : 0);
                int col = wn * 32 + ni * 8 + 2 * ctg + (e & 1);
                float v = (col <= row) ? __expf(acc[mi][ni][e] * 0.125f) : 0.f;
                acc[mi][ni][e] = v;
                rsum[mi][e >> 1] += v;
            }
#pragma unroll
    for (int mi = 0; mi < 4; ++mi)
#pragma unroll
        for (int hl = 0; hl < 2; ++hl) {
            float s = rsum[mi][hl];
            s += __shfl_xor_sync(0xffffffffu, s, 1);
            s += __shfl_xor_sync(0xffffffffu, s, 2);
            rsum[mi][hl] = s;
        }
    if (ctg == 0)
#pragma unroll
        for (int mi = 0; mi < 4; ++mi)
#pragma unroll
            for (int hl = 0; hl < 2; ++hl)
                red[(wm * 64 + mi * 16 + gr + hl * 8) * 4 + wn] = rsum[mi][hl];
    __syncthreads();   // Qs/Ks reads done; red complete

    // load V into Q region ([key][d], natural layout)
    for (int i = tid; i < 1024; i += 256) {
        int r = i >> 3, c8 = (i & 7) << 3;
        *(uint4*)&Vs[r * QPH + c8] = *(const uint4*)(vp + (size_t)r * N_QKV + c8);
    }

    // P = e / (rowsum + 1e-6), fp16 into Ps
#pragma unroll
    for (int mi = 0; mi < 4; ++mi)
#pragma unroll
        for (int hl = 0; hl < 2; ++hl) {
            int row = wm * 64 + mi * 16 + gr + hl * 8;
            float ssum = red[row * 4 + 0] + red[row * 4 + 1]
                       + red[row * 4 + 2] + red[row * 4 + 3];
            float inv = __fdividef(1.f, ssum + 1e-6f);
#pragma unroll
            for (int ni = 0; ni < 4; ++ni) {
                __half2 pv = __floats2half2_rn(acc[mi][ni][hl * 2 + 0] * inv,
                                               acc[mi][ni][hl * 2 + 1] * inv);
                *(__half2*)&Ps[row * PPH + wn * 32 + ni * 8 + 2 * ctg] = pv;
            }
        }
    __syncthreads();

    // O = P @ V (warp tile 64x16, k=128 -> 8 ksteps); V^T frags via ldmatrix.trans
    float oa[4][2][4] = {};
#pragma unroll
    for (int kk = 0; kk < 8; ++kk) {
        const uint32_t kbP = (uint32_t)(kk * 16) * 2;
        uint32_t a[4][4], bfr[2][2];
#pragma unroll
        for (int mi = 0; mi < 4; ++mi)
            LDSM4(a[mi][0], a[mi][1], a[mi][2], a[mi][3],
                  uP + aOffP + (uint32_t)(mi * 16 * PPH) * 2 + kbP);
        LDSM4T(bfr[0][0], bfr[0][1], bfr[1][0], bfr[1][1],
               uV + bOffV + (uint32_t)(kk * 16 * QPH) * 2);
#pragma unroll
        for (int mi = 0; mi < 4; ++mi)
#pragma unroll
            for (int ni = 0; ni < 2; ++ni)
                mma_f16(oa[mi][ni], a[mi], bfr[ni]);
    }

    // store fp16 (feeds GEMM2)
    __half* op = outp + (size_t)token0 * C_ + h * Dh_;
#pragma unroll
    for (int mi = 0; mi < 4; ++mi) {
        int r0 = wm * 64 + mi * 16 + gr;
#pragma unroll
        for (int ni = 0; ni < 2; ++ni) {
            int c0 = wn * 16 + ni * 8 + 2 * ctg;
            __half2 v0 = __floats2half2_rn(oa[mi][ni][0], oa[mi][ni][1]);
            __half2 v1 = __floats2half2_rn(oa[mi][ni][2], oa[mi][ni][3]);
            *(__half2*)&op[(size_t)r0 * C_ + c0]       = v0;
            *(__half2*)&op[(size_t)(r0 + 8) * C_ + c0] = v1;
        }
    }
}

// ---------------------------------------------------------------------------
extern "C" void kernel_launch(void* const* d_in, const int* in_sizes, int n_in,
                              void* d_out, int out_size)
{
    const float* x      = (const float*)d_in[0];
    const float* W_qkv  = (const float*)d_in[1];
    const float* W_proj = (const float*)d_in[2];
    const float* b_proj = (const float*)d_in[3];
    float* out = (float*)d_out;

    __half *qkvh, *attnh, *xh, *WqkvT, *WprojT;
    cudaGetSymbolAddress((void**)&qkvh,   g_qkvh);
    cudaGetSymbolAddress((void**)&attnh,  g_attnh);
    cudaGetSymbolAddress((void**)&xh,     g_xh);
    cudaGetSymbolAddress((void**)&WqkvT,  g_WqkvT);
    cudaGetSymbolAddress((void**)&WprojT, g_WprojT);

    static bool attr_set = false;
    if (!attr_set) {
        cudaFuncSetAttribute((const void*)gemm_h<false, true>,
                             cudaFuncAttributeMaxDynamicSharedMemorySize, GSMEM_B);
        cudaFuncSetAttribute((const void*)gemm_h<true, false>,
                             cudaFuncAttributeMaxDynamicSharedMemorySize, GSMEM_B);
        cudaFuncSetAttribute((const void*)attn_h,
                             cudaFuncAttributeMaxDynamicSharedMemorySize, ATT_B);
        attr_set = true;
    }

    // 0) fp16 conversions
    cvt_f2h<<<(M_TOK * C_ / 4 + 255) / 256, 256>>>((const float4*)x, (uint2*)xh,
                                                   M_TOK * C_ / 4);
    transpose_cvt<<<dim3(N_QKV / 32, KDIM / 32), dim3(32, 8)>>>(W_qkv, WqkvT, KDIM, N_QKV);
    transpose_cvt<<<dim3(C_ / 32, KDIM / 32), dim3(32, 8)>>>(W_proj, WprojT, KDIM, C_);

    // 1) qkv = x @ W_qkv  (fp16 mma, fp16 out)
    gemm_h<false, true><<<dim3(N_QKV / 128, M_TOK / 128), 256, GSMEM_B>>>(
        xh, WqkvT, nullptr, qkvh, N_QKV);

    // 2) block-local causal attention (fp16 mma)
    attn_h<<<dim3(H_, T_ / BS_, B_), 256, ATT_B>>>(qkvh, attnh);

    // 3) out = attn @ W_proj + b_proj (fp16 mma, fp32 out)
    gemm_h<true, false><<<dim3(C_ / 128, M_TOK / 128), 256, GSMEM_B>>>(
        attnh, WprojT, b_proj, out, C_);
}